// round 1
// baseline (speedup 1.0000x reference)
#include <cuda_runtime.h>

// Deriv2Matern52: out[i,a,j,b] = c^2 * ( (a==b)*A(i,j)*inv_l2[a] - 5*fr(i,j)*D[i,j,a]*D[i,j,b] )
//   dx[a]   = X1[i,a] - X2[j,a]
//   r       = sqrt( sum_a dx[a]^2 * inv_l2[a] )
//   fr      = (5/3) * exp(-sqrt5 * r)
//   A       = fr * (1 + sqrt5 * r)
//   D[a]    = dx[a] * inv_l2[a]
//
// Output layout: out[((i*8 + a)*m + j)*8 + b]  (b fastest). One thread per (i,j),
// lanes span j -> per-a the warp writes 1KB contiguous via 2x STG.128 per lane.

#define D_DIM 8
#define SQRT5F 2.2360679774997896f

__global__ __launch_bounds__(256) void deriv2_matern52_kernel(
    const float* __restrict__ X1,   // [n, 8]
    const float* __restrict__ X2,   // [m, 8]
    const float* __restrict__ cptr, // [1]
    const float* __restrict__ lptr, // [8]
    float* __restrict__ out,        // [n, 8, m, 8]
    int n, int m)
{
    int gid = blockIdx.x * blockDim.x + threadIdx.x;
    if (gid >= n * m) return;
    int i = gid / m;
    int j = gid - i * m;

    // lengthscales -> inv_l2 (broadcast loads, L1-resident)
    float invl2[D_DIM];
#pragma unroll
    for (int a = 0; a < D_DIM; a++) {
        float lv = __ldg(lptr + a);
        invl2[a] = 1.0f / (lv * lv);
    }
    float cv = __ldg(cptr);
    float c2 = cv * cv;

    // load X1 row (uniform in warp) and X2 row (per-lane, coalesced) as float4
    float4 x1a = __ldg(reinterpret_cast<const float4*>(X1 + (size_t)i * D_DIM));
    float4 x1b = __ldg(reinterpret_cast<const float4*>(X1 + (size_t)i * D_DIM) + 1);
    float4 x2a = __ldg(reinterpret_cast<const float4*>(X2 + (size_t)j * D_DIM));
    float4 x2b = __ldg(reinterpret_cast<const float4*>(X2 + (size_t)j * D_DIM) + 1);

    float dx[D_DIM];
    dx[0] = x1a.x - x2a.x; dx[1] = x1a.y - x2a.y;
    dx[2] = x1a.z - x2a.z; dx[3] = x1a.w - x2a.w;
    dx[4] = x1b.x - x2b.x; dx[5] = x1b.y - x2b.y;
    dx[6] = x1b.z - x2b.z; dx[7] = x1b.w - x2b.w;

    float s = 0.0f;
    float Dv[D_DIM];
#pragma unroll
    for (int a = 0; a < D_DIM; a++) {
        Dv[a] = dx[a] * invl2[a];
        s = fmaf(dx[a] * dx[a], invl2[a], s);
    }
    float r  = sqrtf(s);
    float fr = (5.0f / 3.0f) * expf(-SQRT5F * r);
    float A  = fr * fmaf(SQRT5F, r, 1.0f);

    float Ac2   = c2 * A;
    float m5fr  = -5.0f * fr * c2;

    // per-a row of 8 outputs, written as two float4s
    size_t base_i = ((size_t)i * D_DIM) * (size_t)m + (size_t)j; // element index of (i, a=0, j, b=0) / 8
#pragma unroll
    for (int a = 0; a < D_DIM; a++) {
        float ta = m5fr * Dv[a];
        float o[D_DIM];
#pragma unroll
        for (int b = 0; b < D_DIM; b++)
            o[b] = ta * Dv[b];
        o[a] = fmaf(Ac2, invl2[a], o[a]);

        float4* dst = reinterpret_cast<float4*>(out + (base_i + (size_t)a * m) * D_DIM);
        float4 v0 = make_float4(o[0], o[1], o[2], o[3]);
        float4 v1 = make_float4(o[4], o[5], o[6], o[7]);
        dst[0] = v0;
        dst[1] = v1;
    }
}

extern "C" void kernel_launch(void* const* d_in, const int* in_sizes, int n_in,
                              void* d_out, int out_size)
{
    const float* X1 = (const float*)d_in[0];
    const float* X2 = (const float*)d_in[1];
    const float* c  = (const float*)d_in[2];
    const float* l  = (const float*)d_in[3];
    float* out = (float*)d_out;

    int n = in_sizes[0] / D_DIM;
    int m = in_sizes[1] / D_DIM;

    int total = n * m;
    int threads = 256;
    int blocks = (total + threads - 1) / threads;
    deriv2_matern52_kernel<<<blocks, threads>>>(X1, X2, c, l, out, n, m);
}

// round 2
// speedup vs baseline: 1.7256x; 1.7256x over previous
#include <cuda_runtime.h>

// Deriv2Matern52: out[i,a,j,b] = c^2 * ( (a==b)*A(i,j)*inv_l2[a] - 5*fr(i,j)*D[i,j,a]*D[i,j,b] )
// Two-phase block structure to make every STG.128 warp-instruction fully
// contiguous (512B, full 32B sectors):
//   phase 1: 128 threads compute per-(i,j) pair data into smem
//   phase 2: 256 threads map 1:1 onto output float4s (thread t -> j=t/2, half=t&1),
//            loop over a, one coalesced STG.128 per a.

#define D_DIM 8
#define JT 128          // j-tile per block
#define SSTRIDE 17      // smem row stride in floats (coprime with 32 banks)
#define SQRT5F 2.2360679774997896f

__global__ __launch_bounds__(256) void deriv2_matern52_kernel(
    const float* __restrict__ X1,   // [n, 8]
    const float* __restrict__ X2,   // [m, 8]
    const float* __restrict__ cptr, // [1]
    const float* __restrict__ lptr, // [8]
    float* __restrict__ out,        // [n, 8, m, 8]
    int m)
{
    __shared__ float sp[JT * SSTRIDE];
    // sp[j*17 + 0..7]  = Dv[a]      (dx[a] * inv_l2[a])
    // sp[j*17 + 8]     = -5 * fr * c^2
    // sp[j*17 + 9..16] = A * c^2 * inv_l2[a]   (diagonal terms)

    const int t  = threadIdx.x;
    const int i  = blockIdx.y;
    const int j0 = blockIdx.x * JT;

    // ---------------- phase 1: pair data ----------------
    if (t < JT) {
        float invl2[D_DIM];
#pragma unroll
        for (int a = 0; a < D_DIM; a++) {
            float lv = __ldg(lptr + a);
            invl2[a] = 1.0f / (lv * lv);
        }
        float cv = __ldg(cptr);
        float c2 = cv * cv;

        const float4* x1p = reinterpret_cast<const float4*>(X1 + (size_t)i * D_DIM);
        const float4* x2p = reinterpret_cast<const float4*>(X2 + (size_t)(j0 + t) * D_DIM);
        float4 x1a = __ldg(x1p);
        float4 x1b = __ldg(x1p + 1);
        float4 x2a = __ldg(x2p);
        float4 x2b = __ldg(x2p + 1);

        float dx[D_DIM];
        dx[0] = x1a.x - x2a.x; dx[1] = x1a.y - x2a.y;
        dx[2] = x1a.z - x2a.z; dx[3] = x1a.w - x2a.w;
        dx[4] = x1b.x - x2b.x; dx[5] = x1b.y - x2b.y;
        dx[6] = x1b.z - x2b.z; dx[7] = x1b.w - x2b.w;

        float s = 0.0f;
        float* row = sp + t * SSTRIDE;
#pragma unroll
        for (int a = 0; a < D_DIM; a++) {
            float dv = dx[a] * invl2[a];
            row[a] = dv;
            s = fmaf(dx[a], dv, s);
        }
        float r   = sqrtf(s);
        float fr  = (5.0f / 3.0f) * expf(-SQRT5F * r);
        float A   = fr * fmaf(SQRT5F, r, 1.0f);
        float Ac2 = A * c2;
        row[8] = -5.0f * fr * c2;
#pragma unroll
        for (int a = 0; a < D_DIM; a++)
            row[9 + a] = Ac2 * invl2[a];
    }
    __syncthreads();

    // ---------------- phase 2: coalesced stores ----------------
    // thread t -> pair p = t/2, half = t&1 (b in [half*4, half*4+4))
    const int p    = t >> 1;
    const int half = t & 1;
    const int hb   = half * 4;

    const float* row = sp + p * SSTRIDE;
    float Dv[D_DIM];
#pragma unroll
    for (int a = 0; a < D_DIM; a++)
        Dv[a] = row[a];
    const float m5 = row[8];
    float Ad[4];
#pragma unroll
    for (int x = 0; x < 4; x++)
        Ad[x] = row[9 + hb + x];

    // base element index of (i, a=0, j0+p, b=hb)
    float* dst = out + ((((size_t)i * D_DIM) * (size_t)m + (size_t)(j0 + p)) * D_DIM) + hb;
    const size_t astride = (size_t)m * D_DIM;

#pragma unroll
    for (int a = 0; a < D_DIM; a++) {
        float ta = m5 * Dv[a];
        float o0 = ta * Dv[hb + 0];
        float o1 = ta * Dv[hb + 1];
        float o2 = ta * Dv[hb + 2];
        float o3 = ta * Dv[hb + 3];
        if ((a >> 2) == half) {
            int x = a & 3;
            float add = Ad[x];
            if (x == 0) o0 += add;
            else if (x == 1) o1 += add;
            else if (x == 2) o2 += add;
            else o3 += add;
        }
        *reinterpret_cast<float4*>(dst + (size_t)a * astride) = make_float4(o0, o1, o2, o3);
    }
}

extern "C" void kernel_launch(void* const* d_in, const int* in_sizes, int n_in,
                              void* d_out, int out_size)
{
    const float* X1 = (const float*)d_in[0];
    const float* X2 = (const float*)d_in[1];
    const float* c  = (const float*)d_in[2];
    const float* l  = (const float*)d_in[3];
    float* out = (float*)d_out;

    int n = in_sizes[0] / D_DIM;
    int m = in_sizes[1] / D_DIM;

    dim3 grid(m / JT, n);
    deriv2_matern52_kernel<<<grid, 256>>>(X1, X2, c, l, out, m);
}

// round 3
// speedup vs baseline: 1.7483x; 1.0131x over previous
#include <cuda_runtime.h>

// Deriv2Matern52: out[i,a,j,b] = c^2 * ( (a==b)*A(i,j)*inv_l2[a] - 5*fr(i,j)*D[i,j,a]*D[i,j,b] )
// Two-phase block structure:
//   phase 1: JT threads compute per-(i,j) pair data into smem
//   phase 2: 2*JT threads map 1:1 onto output float4 half-rows
//            (thread t -> pair p=t/2, half=t&1), loop over a, one fully
//            coalesced 512B-per-warp streaming store (st.global.cs) per a.
// Output is write-once streaming data: evict-first policy avoids L2 churn.

#define D_DIM 8
#define JT 256          // j-tile per block (phase1 threads)
#define NTHREADS 512    // = 2*JT (phase2 threads)
#define SSTRIDE 17      // smem row stride in floats (coprime with 32 banks)
#define SQRT5F 2.2360679774997896f

__global__ __launch_bounds__(NTHREADS) void deriv2_matern52_kernel(
    const float* __restrict__ X1,   // [n, 8]
    const float* __restrict__ X2,   // [m, 8]
    const float* __restrict__ cptr, // [1]
    const float* __restrict__ lptr, // [8]
    float* __restrict__ out,        // [n, 8, m, 8]
    int m)
{
    __shared__ float sp[JT * SSTRIDE];
    // sp[p*17 + 0..7]  = Dv[a]      (dx[a] * inv_l2[a])
    // sp[p*17 + 8]     = -5 * fr * c^2
    // sp[p*17 + 9..16] = A * c^2 * inv_l2[a]   (diagonal terms)

    const int t  = threadIdx.x;
    const int i  = blockIdx.y;
    const int j0 = blockIdx.x * JT;

    // ---------------- phase 1: pair data ----------------
    if (t < JT) {
        float invl2[D_DIM];
#pragma unroll
        for (int a = 0; a < D_DIM; a++) {
            float lv = __ldg(lptr + a);
            invl2[a] = 1.0f / (lv * lv);
        }
        float cv = __ldg(cptr);
        float c2 = cv * cv;

        const float4* x1p = reinterpret_cast<const float4*>(X1 + (size_t)i * D_DIM);
        const float4* x2p = reinterpret_cast<const float4*>(X2 + (size_t)(j0 + t) * D_DIM);
        float4 x1a = __ldg(x1p);
        float4 x1b = __ldg(x1p + 1);
        float4 x2a = __ldg(x2p);
        float4 x2b = __ldg(x2p + 1);

        float dx[D_DIM];
        dx[0] = x1a.x - x2a.x; dx[1] = x1a.y - x2a.y;
        dx[2] = x1a.z - x2a.z; dx[3] = x1a.w - x2a.w;
        dx[4] = x1b.x - x2b.x; dx[5] = x1b.y - x2b.y;
        dx[6] = x1b.z - x2b.z; dx[7] = x1b.w - x2b.w;

        float s = 0.0f;
        float* row = sp + t * SSTRIDE;
#pragma unroll
        for (int a = 0; a < D_DIM; a++) {
            float dv = dx[a] * invl2[a];
            row[a] = dv;
            s = fmaf(dx[a], dv, s);
        }
        float r   = sqrtf(s);
        float fr  = (5.0f / 3.0f) * expf(-SQRT5F * r);
        float A   = fr * fmaf(SQRT5F, r, 1.0f);
        float Ac2 = A * c2;
        row[8] = -5.0f * fr * c2;
#pragma unroll
        for (int a = 0; a < D_DIM; a++)
            row[9 + a] = Ac2 * invl2[a];
    }
    __syncthreads();

    // ---------------- phase 2: coalesced streaming stores ----------------
    // thread t -> pair p = t/2, half = t&1 (b in [half*4, half*4+4))
    const int p    = t >> 1;
    const int half = t & 1;
    const int hb   = half * 4;

    const float* row = sp + p * SSTRIDE;
    float Dv[D_DIM];
#pragma unroll
    for (int a = 0; a < D_DIM; a++)
        Dv[a] = row[a];
    const float m5 = row[8];
    float Ad[4];
#pragma unroll
    for (int x = 0; x < 4; x++)
        Ad[x] = row[9 + hb + x];

    // base element index of (i, a=0, j0+p, b=hb)
    float* dst = out + ((((size_t)i * D_DIM) * (size_t)m + (size_t)(j0 + p)) * D_DIM) + hb;
    const size_t astride = (size_t)m * D_DIM;

#pragma unroll
    for (int a = 0; a < D_DIM; a++) {
        float ta = m5 * Dv[a];
        float o0 = ta * Dv[hb + 0];
        float o1 = ta * Dv[hb + 1];
        float o2 = ta * Dv[hb + 2];
        float o3 = ta * Dv[hb + 3];
        if ((a >> 2) == half) {
            int x = a & 3;
            float add = Ad[x];
            if (x == 0) o0 += add;
            else if (x == 1) o1 += add;
            else if (x == 2) o2 += add;
            else o3 += add;
        }
        __stcs(reinterpret_cast<float4*>(dst + (size_t)a * astride),
               make_float4(o0, o1, o2, o3));
    }
}

extern "C" void kernel_launch(void* const* d_in, const int* in_sizes, int n_in,
                              void* d_out, int out_size)
{
    const float* X1 = (const float*)d_in[0];
    const float* X2 = (const float*)d_in[1];
    const float* c  = (const float*)d_in[2];
    const float* l  = (const float*)d_in[3];
    float* out = (float*)d_out;

    int n = in_sizes[0] / D_DIM;
    int m = in_sizes[1] / D_DIM;

    dim3 grid(m / JT, n);
    deriv2_matern52_kernel<<<grid, NTHREADS>>>(X1, X2, c, l, out, m);
}